// round 14
// baseline (speedup 1.0000x reference)
#include <cuda_runtime.h>
#include <cuda_bf16.h>
#include <cstdint>

#define BB 16
#define CC 256
#define HW 4096
#define NH 8
#define HD 32
#define NG 32
#define CPG 8
#define EPSV 1e-5f
#define SPLIT 32           // n-tiles (slice = 128)

// ---------------- scratch (device globals) ----------------------------------
__device__ __nv_bfloat16 g_xh[(size_t)BB * CC * HW];     // normed x hi
__device__ __nv_bfloat16 g_xl[(size_t)BB * CC * HW];     // normed x lo
__device__ __nv_bfloat16 g_wqh[2 * CC * CC];             // K,V weights hi (rearranged)
__device__ __nv_bfloat16 g_wql[2 * CC * CC];             // K,V weights lo
__device__ float g_att_part[(size_t)BB * NH * SPLIT * HD * HD];  // [bh][s][d*e]
__device__ float g_lmax[SPLIT * BB * NH * HD];
__device__ float g_lsum[SPLIT * BB * NH * HD];
__device__ float g_weff[(size_t)BB * CC * CC];
__device__ __nv_bfloat16 g_w2h[(size_t)BB * CC * CC];
__device__ __nv_bfloat16 g_w2l[(size_t)BB * CC * CC];

// ---------------- warp-MMA helpers ------------------------------------------
__device__ __forceinline__ uint32_t smem_u32(const void* p) {
    uint32_t a;
    asm("{ .reg .u64 t; cvta.to.shared.u64 t, %1; cvt.u32.u64 %0, t; }"
        : "=r"(a) : "l"(p));
    return a;
}
__device__ __forceinline__ void ldmx4(uint32_t* r, uint32_t addr) {
    asm volatile("ldmatrix.sync.aligned.m8n8.x4.shared.b16 {%0,%1,%2,%3}, [%4];"
                 : "=r"(r[0]), "=r"(r[1]), "=r"(r[2]), "=r"(r[3]) : "r"(addr));
}
__device__ __forceinline__ void ldmx4t(uint32_t* r, uint32_t addr) {
    asm volatile("ldmatrix.sync.aligned.m8n8.x4.trans.shared.b16 {%0,%1,%2,%3}, [%4];"
                 : "=r"(r[0]), "=r"(r[1]), "=r"(r[2]), "=r"(r[3]) : "r"(addr));
}
__device__ __forceinline__ void ldmx2(uint32_t* r, uint32_t addr) {
    asm volatile("ldmatrix.sync.aligned.m8n8.x2.shared.b16 {%0,%1}, [%2];"
                 : "=r"(r[0]), "=r"(r[1]) : "r"(addr));
}
__device__ __forceinline__ void mma_bf16(float* c, const uint32_t* a, const uint32_t* b) {
    asm volatile("mma.sync.aligned.m16n8k16.row.col.f32.bf16.bf16.f32 "
                 "{%0,%1,%2,%3}, {%4,%5,%6,%7}, {%8,%9}, {%0,%1,%2,%3};"
                 : "+f"(c[0]), "+f"(c[1]), "+f"(c[2]), "+f"(c[3])
                 : "r"(a[0]), "r"(a[1]), "r"(a[2]), "r"(a[3]),
                   "r"(b[0]), "r"(b[1]));
}
__device__ __forceinline__ uint32_t pk2(__nv_bfloat16 a, __nv_bfloat16 b) {
    __nv_bfloat162 t = __halves2bfloat162(a, b);
    return *(uint32_t*)&t;
}
__device__ __forceinline__ void cp16(uint32_t dst, const void* src) {
    asm volatile("cp.async.cg.shared.global [%0], [%1], 16;" :: "r"(dst), "l"(src));
}

#define AST 40    // A smem row stride (bf16)
#define BST 136   // B smem row stride (bf16)
#define PST 72    // P-stage plane row stride (bf16)

// fused kernel smem layout (3 stages)
#define F_AH 0
#define F_AL 20480
#define F_BH 40960
#define F_BL 49664
#define F_STAGE 58368
#define F_SMEM  (3 * F_STAGE)      // 175104
#define PKH 0
#define PKL 18432
#define PVH 36864
#define PVL 55296
#define PMAX 73728                 // float[2][128]
#define PSUM 74752                 // float[2][128]

// final gemm smem layout (3 stages)
#define ST_AH 0
#define ST_AL 10240
#define ST_BH 20480
#define ST_BL 29184
#define ST_BYTES 37888
#define SMEM_GEMM (3 * ST_BYTES)   // 113664

// ---------------------------------------------------------------------------
// K1: fused GroupNorm (stats + apply) + bf16 hi/lo split of x (L2 re-read).
// ---------------------------------------------------------------------------
__global__ __launch_bounds__(256)
void gn_prep_kernel(const float* __restrict__ x,
                    const float* __restrict__ gw,
                    const float* __restrict__ gb) {
    const int b = blockIdx.x / NG;
    const int g = blockIdx.x % NG;
    const size_t base = ((size_t)b * CC + (size_t)g * CPG) * HW;
    const float* xp = x + base;
    const int tid = threadIdx.x;

    float s = 0.f, s2 = 0.f;
    #pragma unroll 8
    for (int it = 0; it < 32; it++) {
        float4 v = *(const float4*)(xp + (size_t)(it * 256 + tid) * 4);
        s  += v.x + v.y + v.z + v.w;
        s2 += v.x * v.x + v.y * v.y + v.z * v.z + v.w * v.w;
    }
    __shared__ float rs[32], rs2[32];
    #pragma unroll
    for (int o = 16; o > 0; o >>= 1) {
        s  += __shfl_down_sync(0xFFFFFFFFu, s,  o);
        s2 += __shfl_down_sync(0xFFFFFFFFu, s2, o);
    }
    int lane = tid & 31, wid = tid >> 5;
    if (lane == 0) { rs[wid] = s; rs2[wid] = s2; }
    __syncthreads();
    if (wid == 0) {
        s  = (lane < 8) ? rs[lane]  : 0.f;
        s2 = (lane < 8) ? rs2[lane] : 0.f;
        #pragma unroll
        for (int o = 4; o > 0; o >>= 1) {
            s  += __shfl_down_sync(0xFFFFFFFFu, s,  o);
            s2 += __shfl_down_sync(0xFFFFFFFFu, s2, o);
        }
        if (lane == 0) { rs[0] = s; rs2[0] = s2; }
    }
    __syncthreads();
    const float inv_n = 1.f / (float)(CPG * HW);
    const float mu   = rs[0] * inv_n;
    const float var  = rs2[0] * inv_n - mu * mu;
    const float rstd = rsqrtf(var + EPSV);

    __shared__ float ssc[CPG], ssh[CPG];
    if (tid < CPG) {
        int c = g * CPG + tid;
        float scv = rstd * gw[c];
        ssc[tid] = scv;
        ssh[tid] = gb[c] - mu * scv;
    }
    __syncthreads();

    __nv_bfloat16* xh = g_xh + base;
    __nv_bfloat16* xl = g_xl + base;
    #pragma unroll 8
    for (int it = 0; it < 32; it++) {
        int idx = it * 256 + tid;            // float4 index; 1024 per row
        int row = idx >> 10;
        float sc = ssc[row], sh = ssh[row];
        float4 v = *(const float4*)(xp + (size_t)idx * 4);
        v.x = fmaf(v.x, sc, sh); v.y = fmaf(v.y, sc, sh);
        v.z = fmaf(v.z, sc, sh); v.w = fmaf(v.w, sc, sh);
        __nv_bfloat16 h0 = __float2bfloat16(v.x), h1 = __float2bfloat16(v.y);
        __nv_bfloat16 h2 = __float2bfloat16(v.z), h3 = __float2bfloat16(v.w);
        __nv_bfloat16 l0 = __float2bfloat16(v.x - __bfloat162float(h0));
        __nv_bfloat16 l1 = __float2bfloat16(v.y - __bfloat162float(h1));
        __nv_bfloat16 l2 = __float2bfloat16(v.z - __bfloat162float(h2));
        __nv_bfloat16 l3 = __float2bfloat16(v.w - __bfloat162float(h3));
        *(uint2*)(xh + (size_t)idx * 4) = make_uint2(pk2(h0, h1), pk2(h2, h3));
        *(uint2*)(xl + (size_t)idx * 4) = make_uint2(pk2(l0, l1), pk2(l2, l3));
    }
}

// K1c: split + rearrange w_qkv K,V rows
__global__ __launch_bounds__(256) void prep_w_kernel(const float* __restrict__ w) {
    int idx = blockIdx.x * 256 + threadIdx.x;   // 0 .. 32767 float4s
    int r = idx >> 6, c4 = (idx & 63) * 4;
    int hh = r >> 8, rr = r & 255;
    int src = (rr < 128) ? (256 + hh * 128 + rr) : (512 + hh * 128 + rr - 128);
    float4 v = *(const float4*)(w + (size_t)src * CC + c4);
    __nv_bfloat16 h0 = __float2bfloat16(v.x), h1 = __float2bfloat16(v.y);
    __nv_bfloat16 h2 = __float2bfloat16(v.z), h3 = __float2bfloat16(v.w);
    __nv_bfloat16 l0 = __float2bfloat16(v.x - __bfloat162float(h0));
    __nv_bfloat16 l1 = __float2bfloat16(v.y - __bfloat162float(h1));
    __nv_bfloat16 l2 = __float2bfloat16(v.z - __bfloat162float(h2));
    __nv_bfloat16 l3 = __float2bfloat16(v.w - __bfloat162float(h3));
    size_t o = (size_t)r * CC + c4;
    *(uint2*)(g_wqh + o) = make_uint2(pk2(h0, h1), pk2(h2, h3));
    *(uint2*)(g_wql + o) = make_uint2(pk2(l0, l1), pk2(l2, l3));
}

// ---------------------------------------------------------------------------
// K2: fused KV GEMM + online attention partials (3-stage cp.async pipeline).
// ---------------------------------------------------------------------------
__global__ __launch_bounds__(512)
void gemm_kv_att() {
    extern __shared__ char smem[];
    const uint32_t sb = smem_u32(smem);

    const int tid = threadIdx.x;
    const int wid = tid >> 5, lane = tid & 31;
    const int wM = wid >> 1, wN = wid & 1;     // wM 0-3 = K rows, 4-7 = V rows
    const int s  = blockIdx.x;
    const int hh = blockIdx.y;
    const int b  = blockIdx.z;
    const int n0 = s * 128;

    const __nv_bfloat16* Ahb = g_wqh + (size_t)hh * 256 * CC;
    const __nv_bfloat16* Alb = g_wql + (size_t)hh * 256 * CC;
    const __nv_bfloat16* Bh  = g_xh + (size_t)b * CC * HW;
    const __nv_bfloat16* Bl  = g_xl + (size_t)b * CC * HW;

    const int bRowL0 = tid >> 4, bQ4 = (tid & 15) * 8;

    auto issue = [&](int kc, int stage) {
        const uint32_t st = sb + stage * F_STAGE;
        const int k0 = kc * 32;
        #pragma unroll
        for (int it = 0; it < 2; it++) {       // A: 1024 cp16 per plane
            int idx = it * 512 + tid;
            int row = idx >> 2, q4 = (idx & 3) * 8;
            uint32_t d = (uint32_t)(row * AST + q4) * 2;
            cp16(st + F_AH + d, Ahb + (size_t)row * CC + k0 + q4);
            cp16(st + F_AL + d, Alb + (size_t)row * CC + k0 + q4);
        }
        {                                      // B: 512 cp16 per plane
            size_t g = ((size_t)(k0 + bRowL0)) * HW + n0 + bQ4;
            uint32_t d = (uint32_t)(bRowL0 * BST + bQ4) * 2;
            cp16(st + F_BH + d, Bh + g);
            cp16(st + F_BL + d, Bl + g);
        }
        asm volatile("cp.async.commit_group;");
    };

    float acc[2][8][4];
    #pragma unroll
    for (int i = 0; i < 2; i++)
        #pragma unroll
        for (int j = 0; j < 8; j++)
            #pragma unroll
            for (int q = 0; q < 4; q++) acc[i][j][q] = 0.f;

    const int lt = lane >> 3, lr = lane & 7;
    const int aRow = lr + ((lt & 1) ? 8 : 0);
    const int aKof = (lt & 2) ? 8 : 0;
    const int bKof = lr + ((lt & 1) ? 8 : 0);
    const int bNof = (lt & 2) ? 8 : 0;

    issue(0, 0);
    issue(1, 1);

    for (int kc = 0; kc < 8; kc++) {
        const int stage = kc % 3;
        if (kc < 6) {
            issue(kc + 2, (kc + 2) % 3);
            asm volatile("cp.async.wait_group 2;");
        } else if (kc == 6) {
            asm volatile("cp.async.wait_group 1;");
        } else {
            asm volatile("cp.async.wait_group 0;");
        }
        __syncthreads();

        const uint32_t aHB = sb + stage * F_STAGE + F_AH;
        const uint32_t aLB = sb + stage * F_STAGE + F_AL;
        const uint32_t bHB = sb + stage * F_STAGE + F_BH;
        const uint32_t bLB = sb + stage * F_STAGE + F_BL;

        #pragma unroll
        for (int ks = 0; ks < 2; ks++) {
            const int kb = ks * 16;
            uint32_t ah[2][4], al[2][4], bh[8][2], bl[8][2];
            #pragma unroll
            for (int mt = 0; mt < 2; mt++) {
                uint32_t ad = ((wM * 32 + mt * 16 + aRow) * AST + kb + aKof) * 2;
                ldmx4(ah[mt], aHB + ad);
                ldmx4(al[mt], aLB + ad);
            }
            #pragma unroll
            for (int np = 0; np < 4; np++) {
                uint32_t bd = ((kb + bKof) * BST + wN * 64 + np * 16 + bNof) * 2;
                uint32_t r[4];
                ldmx4t(r, bHB + bd);
                bh[np * 2][0] = r[0]; bh[np * 2][1] = r[1];
                bh[np * 2 + 1][0] = r[2]; bh[np * 2 + 1][1] = r[3];
                ldmx4t(r, bLB + bd);
                bl[np * 2][0] = r[0]; bl[np * 2][1] = r[1];
                bl[np * 2 + 1][0] = r[2]; bl[np * 2 + 1][1] = r[3];
            }
            #pragma unroll
            for (int mt = 0; mt < 2; mt++)
                #pragma unroll
                for (int nt = 0; nt < 8; nt++) {
                    mma_bf16(acc[mt][nt], ah[mt], bh[nt]);
                    mma_bf16(acc[mt][nt], ah[mt], bl[nt]);
                    mma_bf16(acc[mt][nt], al[mt], bh[nt]);
                }
        }
        __syncthreads();
    }

    // ================= fused attention epilogue =================
    const int rq = lane >> 2, cq = lane & 3;
    const bool isK = (wM < 4);
    float* smMax = (float*)(smem + PMAX);  // [2][128]
    float* smSum = (float*)(smem + PSUM);  // [2][128]

    // 1. per-warp row max over this warp's 64 cols
    if (isK) {
        #pragma unroll
        for (int mt = 0; mt < 2; mt++)
            #pragma unroll
            for (int rh = 0; rh < 2; rh++) {
                float m = -3.4e38f;
                #pragma unroll
                for (int nt = 0; nt < 8; nt++) {
                    m = fmaxf(m, acc[mt][nt][rh * 2]);
                    m = fmaxf(m, acc[mt][nt][rh * 2 + 1]);
                }
                m = fmaxf(m, __shfl_xor_sync(0xFFFFFFFFu, m, 1));
                m = fmaxf(m, __shfl_xor_sync(0xFFFFFFFFu, m, 2));
                if (cq == 0)
                    smMax[wN * 128 + wM * 32 + mt * 16 + rh * 8 + rq] = m;
            }
    }
    __syncthreads();

    // 2. exp with combined max + row sums
    if (isK) {
        #pragma unroll
        for (int mt = 0; mt < 2; mt++)
            #pragma unroll
            for (int rh = 0; rh < 2; rh++) {
                int row = wM * 32 + mt * 16 + rh * 8 + rq;
                float km = fmaxf(smMax[row], smMax[128 + row]);
                float ss = 0.f;
                #pragma unroll
                for (int nt = 0; nt < 8; nt++) {
                    float e0 = __expf(acc[mt][nt][rh * 2]     - km);
                    float e1 = __expf(acc[mt][nt][rh * 2 + 1] - km);
                    acc[mt][nt][rh * 2]     = e0;
                    acc[mt][nt][rh * 2 + 1] = e1;
                    ss += e0 + e1;
                }
                ss += __shfl_xor_sync(0xFFFFFFFFu, ss, 1);
                ss += __shfl_xor_sync(0xFFFFFFFFu, ss, 2);
                if (cq == 0) smSum[wN * 128 + row] = ss;
            }
    }

    // 3. two n-passes: stage expK/V tiles (bf16 hi/lo) + P-MMA
    float pp[2][4];
    #pragma unroll
    for (int mt = 0; mt < 2; mt++)
        #pragma unroll
        for (int q = 0; q < 4; q++) pp[mt][q] = 0.f;

    const int head = wid >> 2, sub = wid & 3;
    const int l16 = lane & 15;
    const uint32_t baddrBase =
        ((head * 32 + sub * 8 + (l16 & 7)) * PST + (l16 >> 3) * 8) * 2;

    #pragma unroll
    for (int p = 0; p < 2; p++) {
        __syncthreads();
        if (wN == p) {
            const int rowb = (wM & 3) * 32;
            #pragma unroll
            for (int mt = 0; mt < 2; mt++)
                #pragma unroll
                for (int rh = 0; rh < 2; rh++) {
                    int row = rowb + mt * 16 + rh * 8 + rq;
                    #pragma unroll
                    for (int nt = 0; nt < 8; nt++) {
                        int c = nt * 8 + cq * 2;
                        float v0 = acc[mt][nt][rh * 2];
                        float v1 = acc[mt][nt][rh * 2 + 1];
                        __nv_bfloat16 h0 = __float2bfloat16(v0);
                        __nv_bfloat16 h1 = __float2bfloat16(v1);
                        __nv_bfloat16 q0 = __float2bfloat16(v0 - __bfloat162float(h0));
                        __nv_bfloat16 q1 = __float2bfloat16(v1 - __bfloat162float(h1));
                        uint32_t off = (uint32_t)(row * PST + c) * 2;
                        *(uint32_t*)(smem + (isK ? PKH : PVH) + off) = pk2(h0, h1);
                        *(uint32_t*)(smem + (isK ? PKL : PVL) + off) = pk2(q0, q1);
                    }
                }
        }
        __syncthreads();

        #pragma unroll
        for (int ks = 0; ks < 4; ks++) {
            const int kb = ks * 16;
            uint32_t b2h[2], b2l[2];
            ldmx2(b2h, sb + PVH + baddrBase + (uint32_t)kb * 2);
            ldmx2(b2l, sb + PVL + baddrBase + (uint32_t)kb * 2);
            #pragma unroll
            for (int mt = 0; mt < 2; mt++) {
                uint32_t a2h[4], a2l[4];
                uint32_t ad = ((head * 32 + mt * 16 + aRow) * PST + kb + aKof) * 2;
                ldmx4(a2h, sb + PKH + ad);
                ldmx4(a2l, sb + PKL + ad);
                mma_bf16(pp[mt], a2h, b2h);
                mma_bf16(pp[mt], a2h, b2l);
                mma_bf16(pp[mt], a2l, b2h);
            }
        }
    }

    // 4. write P partials ([bh][s][d*e] layout), lmax, lsum
    const int bh = b * NH + hh * 4 + head;
    float* P = g_att_part + ((size_t)bh * SPLIT + s) * (HD * HD);
    #pragma unroll
    for (int mt = 0; mt < 2; mt++) {
        int d = mt * 16 + rq;
        int e = sub * 8 + cq * 2;
        *(float2*)&P[d * HD + e]       = make_float2(pp[mt][0], pp[mt][1]);
        *(float2*)&P[(d + 8) * HD + e] = make_float2(pp[mt][2], pp[mt][3]);
    }
    if (tid < 128) {
        int h = hh * 4 + (tid >> 5);
        int o = (s * (BB * NH) + b * NH + h) * HD + (tid & 31);
        g_lmax[o] = fmaxf(smMax[tid], smMax[128 + tid]);
        g_lsum[o] = smSum[tid] + smSum[128 + tid];
    }
}

// ---------------------------------------------------------------------------
// K3: fused split-combine + Weff slice.  Grid (128 bh, 4 d-groups), 256 thr.
//   Block (bh, dg) owns att rows [dg*8, dg*8+8). 4 s-groups reduce in regs,
//   combine in smem (fixed order), then fold into Weff columns for those d.
// ---------------------------------------------------------------------------
__global__ __launch_bounds__(256) void att_weff_kernel(const float* __restrict__ wp) {
    const int bh = blockIdx.x, dg = blockIdx.y;
    const int b = bh >> 3, h = bh & 7;
    const int t = threadIdx.x;

    __shared__ float sfac[SPLIT][8];      // 1 KB
    __shared__ float sdinv[8];
    __shared__ float satt[8 * HD];        // 1 KB slab (rows dg*8..+8)
    __shared__ float spart[3][8 * HD];    // 3 KB partials (groups 1..3)

    if (t < 8) {
        int d = dg * 8 + t;
        float gm = -3.4e38f;
        #pragma unroll 4
        for (int s = 0; s < SPLIT; s++)
            gm = fmaxf(gm, g_lmax[(s * (BB * NH) + bh) * HD + d]);
        float den = 0.f;
        #pragma unroll 4
        for (int s = 0; s < SPLIT; s++) {
            float f = __expf(g_lmax[(s * (BB * NH) + bh) * HD + d] - gm);
            sfac[s][t] = f;
            den += g_lsum[(s * (BB * NH) + bh) * HD + d] * f;
        }
        sdinv[t] = 1.f / den;
    }
    __syncthreads();

    // P reduce: sg = s-group (8 splits each), pos = float4 within 8x32 slab
    const float4* P4 = (const float4*)(g_att_part + (size_t)bh * SPLIT * (HD * HD));
    const int sg = t >> 6, pos = t & 63;
    const int drow = pos >> 3;            // local d row (8 float4 per row)
    float4 a4 = make_float4(0.f, 0.f, 0.f, 0.f);
    #pragma unroll
    for (int si = 0; si < 8; si++) {
        int s = sg * 8 + si;
        float f = sfac[s][drow];
        float4 p = P4[s * 256 + dg * 64 + pos];
        a4.x = fmaf(p.x, f, a4.x);
        a4.y = fmaf(p.y, f, a4.y);
        a4.z = fmaf(p.z, f, a4.z);
        a4.w = fmaf(p.w, f, a4.w);
    }
    if (sg > 0) *(float4*)&spart[sg - 1][pos * 4] = a4;
    __syncthreads();
    if (sg == 0) {
        float4 p1 = *(const float4*)&spart[0][pos * 4];
        float4 p2 = *(const float4*)&spart[1][pos * 4];
        float4 p3 = *(const float4*)&spart[2][pos * 4];
        float di = sdinv[drow];
        a4.x = (a4.x + p1.x + p2.x + p3.x) * di;
        a4.y = (a4.y + p1.y + p2.y + p3.y) * di;
        a4.z = (a4.z + p1.z + p2.z + p3.z) * di;
        a4.w = (a4.w + p1.w + p2.w + p3.w) * di;
        *(float4*)&satt[pos * 4] = a4;
    }
    __syncthreads();

    // Weff fold: o = t, this block's 8 d-columns
    const float* wrow = wp + (size_t)t * CC + h * HD;
    float wreg[HD];
    #pragma unroll
    for (int e = 0; e < HD; e++) wreg[e] = wrow[e];
    float* wout = g_weff + ((size_t)b * CC + t) * CC + h * HD + dg * 8;
    #pragma unroll
    for (int d2 = 0; d2 < 8; d2++) {
        float sum = 0.f;
        #pragma unroll
        for (int e = 0; e < HD; e++)
            sum = fmaf(wreg[e], satt[d2 * HD + e], sum);
        wout[d2] = sum;
    }
}

// ---------------------------------------------------------------------------
// K4b: W2[b] = Weff[b] . Wq_q, split to bf16 hi/lo
// ---------------------------------------------------------------------------
__global__ __launch_bounds__(256) void w2_kernel(const float* __restrict__ wq) {
    __shared__ float sW[16 * 256];
    const int b = blockIdx.x, r0 = blockIdx.y * 16;
    const int t = threadIdx.x;

    const float4* src = (const float4*)(g_weff + ((size_t)b * CC + r0) * CC);
    #pragma unroll
    for (int i = 0; i < 4; i++)
        ((float4*)sW)[i * 256 + t] = src[i * 256 + t];
    __syncthreads();

    const int c = t;
    float acc[16];
    #pragma unroll
    for (int o = 0; o < 16; o++) acc[o] = 0.f;

    for (int d = 0; d < CC; d += 4) {
        float wv0 = wq[(size_t)(d + 0) * CC + c];
        float wv1 = wq[(size_t)(d + 1) * CC + c];
        float wv2 = wq[(size_t)(d + 2) * CC + c];
        float wv3 = wq[(size_t)(d + 3) * CC + c];
        #pragma unroll
        for (int o = 0; o < 16; o++) {
            float4 sw = *(const float4*)&sW[o * 256 + d];
            acc[o] = fmaf(sw.x, wv0, acc[o]);
            acc[o] = fmaf(sw.y, wv1, acc[o]);
            acc[o] = fmaf(sw.z, wv2, acc[o]);
            acc[o] = fmaf(sw.w, wv3, acc[o]);
        }
    }
    #pragma unroll
    for (int o = 0; o < 16; o++) {
        float v = acc[o];
        __nv_bfloat16 hh = __float2bfloat16(v);
        __nv_bfloat16 ll = __float2bfloat16(v - __bfloat162float(hh));
        size_t g = ((size_t)b * CC + r0 + o) * CC + c;
        g_w2h[g] = hh;
        g_w2l[g] = ll;
    }
}

// ---------------------------------------------------------------------------
// K5: final GEMM out = W2[b] @ xn + bias (256 threads, 3-stage cp.async)
// ---------------------------------------------------------------------------
__global__ __launch_bounds__(256)
void gemm_final(const float* __restrict__ bias, float* __restrict__ Cout) {
    extern __shared__ char smem[];
    const uint32_t sb = smem_u32(smem);

    const int tid = threadIdx.x;
    const int wid = tid >> 5, lane = tid & 31;
    const int wM = wid >> 1, wN = wid & 1;
    const int b  = blockIdx.z;
    const int m0 = blockIdx.y * 128;
    const int n0 = blockIdx.x * 128;

    const __nv_bfloat16* Ahb = g_w2h + (size_t)b * CC * CC;
    const __nv_bfloat16* Alb = g_w2l + (size_t)b * CC * CC;
    const __nv_bfloat16* Bh  = g_xh + (size_t)b * CC * HW;
    const __nv_bfloat16* Bl  = g_xl + (size_t)b * CC * HW;

    const int aRowL0 = tid >> 2, aQ4 = (tid & 3) * 8;
    const int bRowL0 = tid >> 4, bQ4 = (tid & 15) * 8;

    auto issue = [&](int kc, int stage) {
        const uint32_t st = sb + stage * ST_BYTES;
        const int k0 = kc * 32;
        #pragma unroll
        for (int it = 0; it < 2; it++) {
            int row = aRowL0 + it * 64;
            uint32_t d = (uint32_t)(row * AST + aQ4) * 2;
            cp16(st + ST_AH + d, Ahb + (size_t)(m0 + row) * CC + k0 + aQ4);
            cp16(st + ST_AL + d, Alb + (size_t)(m0 + row) * CC + k0 + aQ4);
        }
        #pragma unroll
        for (int it = 0; it < 2; it++) {
            int row = bRowL0 + it * 16;
            size_t g = ((size_t)(k0 + row)) * HW + n0 + bQ4;
            uint32_t d = (uint32_t)(row * BST + bQ4) * 2;
            cp16(st + ST_BH + d, Bh + g);
            cp16(st + ST_BL + d, Bl + g);
        }
        asm volatile("cp.async.commit_group;");
    };

    float acc[2][8][4];
    #pragma unroll
    for (int i = 0; i < 2; i++)
        #pragma unroll
        for (int j = 0; j < 8; j++)
            #pragma unroll
            for (int q = 0; q < 4; q++) acc[i][j][q] = 0.f;

    const int lt = lane >> 3, lr = lane & 7;
    const int aRow = lr + ((lt & 1) ? 8 : 0);
    const int aKof = (lt & 2) ? 8 : 0;
    const int bKof = lr + ((lt & 1) ? 8 : 0);
    const int bNof = (lt & 2) ? 8 : 0;

    issue(0, 0);
    issue(1, 1);

    for (int kc = 0; kc < 8; kc++) {
        const int stage = kc % 3;
        if (kc < 6) {
            issue(kc + 2, (kc + 2) % 3);
            asm volatile("cp.async.wait_group 2;");
        } else if (kc == 6) {
            asm volatile("cp.async.wait_group 1;");
        } else {
            asm volatile("cp.async.wait_group 0;");
        }
        __syncthreads();

        const uint32_t aHB = sb + stage * ST_BYTES + ST_AH;
        const uint32_t aLB = sb + stage * ST_BYTES + ST_AL;
        const uint32_t bHB = sb + stage * ST_BYTES + ST_BH;
        const uint32_t bLB = sb + stage * ST_BYTES + ST_BL;

        #pragma unroll
        for (int ks = 0; ks < 2; ks++) {
            const int kb = ks * 16;
            uint32_t ah[2][4], al[2][4], bh[8][2], bl[8][2];
            #pragma unroll
            for (int mt = 0; mt < 2; mt++) {
                uint32_t ad = ((wM * 32 + mt * 16 + aRow) * AST + kb + aKof) * 2;
                ldmx4(ah[mt], aHB + ad);
                ldmx4(al[mt], aLB + ad);
            }
            #pragma unroll
            for (int np = 0; np < 4; np++) {
                uint32_t bd = ((kb + bKof) * BST + wN * 64 + np * 16 + bNof) * 2;
                uint32_t r[4];
                ldmx4t(r, bHB + bd);
                bh[np * 2][0] = r[0]; bh[np * 2][1] = r[1];
                bh[np * 2 + 1][0] = r[2]; bh[np * 2 + 1][1] = r[3];
                ldmx4t(r, bLB + bd);
                bl[np * 2][0] = r[0]; bl[np * 2][1] = r[1];
                bl[np * 2 + 1][0] = r[2]; bl[np * 2 + 1][1] = r[3];
            }
            #pragma unroll
            for (int mt = 0; mt < 2; mt++)
                #pragma unroll
                for (int nt = 0; nt < 8; nt++) {
                    mma_bf16(acc[mt][nt], ah[mt], bh[nt]);
                    mma_bf16(acc[mt][nt], ah[mt], bl[nt]);
                    mma_bf16(acc[mt][nt], al[mt], bh[nt]);
                }
        }
        __syncthreads();
    }

    const int rbase = m0 + wM * 32 + (lane >> 2);
    const int cbase = n0 + wN * 64 + (lane & 3) * 2;
    #pragma unroll
    for (int mt = 0; mt < 2; mt++) {
        int r0 = rbase + mt * 16;
        float bi0 = bias[r0];
        float bi1 = bias[r0 + 8];
        #pragma unroll
        for (int nt = 0; nt < 8; nt++) {
            int cc = cbase + nt * 8;
            *(float2*)(Cout + ((size_t)b * CC + r0) * HW + cc) =
                make_float2(acc[mt][nt][0] + bi0, acc[mt][nt][1] + bi0);
            *(float2*)(Cout + ((size_t)b * CC + r0 + 8) * HW + cc) =
                make_float2(acc[mt][nt][2] + bi1, acc[mt][nt][3] + bi1);
        }
    }
}

// ---------------------------------------------------------------------------
extern "C" void kernel_launch(void* const* d_in, const int* in_sizes, int n_in,
                              void* d_out, int out_size) {
    const float* x      = (const float*)d_in[0];
    const float* gn_w   = (const float*)d_in[1];
    const float* gn_b   = (const float*)d_in[2];
    const float* w_qkv  = (const float*)d_in[3];
    const float* w_proj = (const float*)d_in[4];
    const float* b_proj = (const float*)d_in[5];
    float* out = (float*)d_out;

    cudaFuncSetAttribute(gemm_kv_att, cudaFuncAttributeMaxDynamicSharedMemorySize,
                         F_SMEM);
    cudaFuncSetAttribute(gemm_final, cudaFuncAttributeMaxDynamicSharedMemorySize,
                         SMEM_GEMM);

    // K1: fused groupnorm + split x; split+rearrange K/V weights
    prep_w_kernel<<<128, 256>>>(w_qkv);
    gn_prep_kernel<<<BB * NG, 256>>>(x, gn_w, gn_b);

    // K2: fused KV projection + attention partials
    {
        dim3 grid(SPLIT, 2, BB);
        gemm_kv_att<<<grid, 512, F_SMEM>>>();
    }

    // K3: combine splits + fold into Wp (grid: bh x 4 d-groups)
    {
        dim3 grid(BB * NH, 4);
        att_weff_kernel<<<grid, 256>>>(w_proj);
    }

    // K4: W2 = Weff . Wq_q
    {
        dim3 grid(BB, CC / 16);
        w2_kernel<<<grid, 256>>>(w_qkv);
    }

    // K5: out = W2[b] @ xn + bias
    {
        dim3 grid(HW / 128, CC / 128, BB);
        gemm_final<<<grid, 256, SMEM_GEMM>>>(b_proj, out);
    }
}

// round 15
// speedup vs baseline: 1.0376x; 1.0376x over previous
#include <cuda_runtime.h>
#include <cuda_bf16.h>
#include <cstdint>

#define BB 16
#define CC 256
#define HW 4096
#define NH 8
#define HD 32
#define NG 32
#define CPG 8
#define EPSV 1e-5f
#define SPLIT 32           // n-tiles (slice = 128)

// ---------------- scratch (device globals) ----------------------------------
__device__ __nv_bfloat16 g_xh[(size_t)BB * CC * HW];     // normed x hi
__device__ __nv_bfloat16 g_xl[(size_t)BB * CC * HW];     // normed x lo
__device__ __nv_bfloat16 g_wqh[2 * CC * CC];             // K,V weights hi (rearranged)
__device__ __nv_bfloat16 g_wql[2 * CC * CC];             // K,V weights lo
__device__ float g_att_part[(size_t)BB * NH * SPLIT * HD * HD];  // [bh][s][d*e]
__device__ float g_lmax[BB * NH * SPLIT * HD];           // [bh][s][d]
__device__ float g_lsum[BB * NH * SPLIT * HD];           // [bh][s][d]
__device__ float g_weff[(size_t)BB * CC * CC];
__device__ __nv_bfloat16 g_w2h[(size_t)BB * CC * CC];
__device__ __nv_bfloat16 g_w2l[(size_t)BB * CC * CC];

// ---------------- warp-MMA helpers ------------------------------------------
__device__ __forceinline__ uint32_t smem_u32(const void* p) {
    uint32_t a;
    asm("{ .reg .u64 t; cvta.to.shared.u64 t, %1; cvt.u32.u64 %0, t; }"
        : "=r"(a) : "l"(p));
    return a;
}
__device__ __forceinline__ void ldmx4(uint32_t* r, uint32_t addr) {
    asm volatile("ldmatrix.sync.aligned.m8n8.x4.shared.b16 {%0,%1,%2,%3}, [%4];"
                 : "=r"(r[0]), "=r"(r[1]), "=r"(r[2]), "=r"(r[3]) : "r"(addr));
}
__device__ __forceinline__ void ldmx4t(uint32_t* r, uint32_t addr) {
    asm volatile("ldmatrix.sync.aligned.m8n8.x4.trans.shared.b16 {%0,%1,%2,%3}, [%4];"
                 : "=r"(r[0]), "=r"(r[1]), "=r"(r[2]), "=r"(r[3]) : "r"(addr));
}
__device__ __forceinline__ void ldmx2(uint32_t* r, uint32_t addr) {
    asm volatile("ldmatrix.sync.aligned.m8n8.x2.shared.b16 {%0,%1}, [%2];"
                 : "=r"(r[0]), "=r"(r[1]) : "r"(addr));
}
__device__ __forceinline__ void mma_bf16(float* c, const uint32_t* a, const uint32_t* b) {
    asm volatile("mma.sync.aligned.m16n8k16.row.col.f32.bf16.bf16.f32 "
                 "{%0,%1,%2,%3}, {%4,%5,%6,%7}, {%8,%9}, {%0,%1,%2,%3};"
                 : "+f"(c[0]), "+f"(c[1]), "+f"(c[2]), "+f"(c[3])
                 : "r"(a[0]), "r"(a[1]), "r"(a[2]), "r"(a[3]),
                   "r"(b[0]), "r"(b[1]));
}
__device__ __forceinline__ uint32_t pk2(__nv_bfloat16 a, __nv_bfloat16 b) {
    __nv_bfloat162 t = __halves2bfloat162(a, b);
    return *(uint32_t*)&t;
}
__device__ __forceinline__ void cp16(uint32_t dst, const void* src) {
    asm volatile("cp.async.cg.shared.global [%0], [%1], 16;" :: "r"(dst), "l"(src));
}

#define AST 40    // A smem row stride (bf16)
#define BST 136   // B smem row stride (bf16)
#define PST 72    // P-stage plane row stride (bf16)

// fused kernel smem layout (3 stages)
#define F_AH 0
#define F_AL 20480
#define F_BH 40960
#define F_BL 49664
#define F_STAGE 58368
#define F_SMEM  (3 * F_STAGE)      // 175104
#define PKH 0
#define PKL 18432
#define PVH 36864
#define PVL 55296
#define PMAX 73728                 // float[2][128]
#define PSUM 74752                 // float[2][128]

// final gemm smem layout (3 stages)
#define ST_AH 0
#define ST_AL 10240
#define ST_BH 20480
#define ST_BL 29184
#define ST_BYTES 37888
#define SMEM_GEMM (3 * ST_BYTES)   // 113664

// ---------------------------------------------------------------------------
// K1: fused GroupNorm (stats + apply) + bf16 hi/lo split of x (L2 re-read).
// ---------------------------------------------------------------------------
__global__ __launch_bounds__(256)
void gn_prep_kernel(const float* __restrict__ x,
                    const float* __restrict__ gw,
                    const float* __restrict__ gb) {
    const int b = blockIdx.x / NG;
    const int g = blockIdx.x % NG;
    const size_t base = ((size_t)b * CC + (size_t)g * CPG) * HW;
    const float* xp = x + base;
    const int tid = threadIdx.x;

    float s = 0.f, s2 = 0.f;
    #pragma unroll 8
    for (int it = 0; it < 32; it++) {
        float4 v = *(const float4*)(xp + (size_t)(it * 256 + tid) * 4);
        s  += v.x + v.y + v.z + v.w;
        s2 += v.x * v.x + v.y * v.y + v.z * v.z + v.w * v.w;
    }
    __shared__ float rs[32], rs2[32];
    #pragma unroll
    for (int o = 16; o > 0; o >>= 1) {
        s  += __shfl_down_sync(0xFFFFFFFFu, s,  o);
        s2 += __shfl_down_sync(0xFFFFFFFFu, s2, o);
    }
    int lane = tid & 31, wid = tid >> 5;
    if (lane == 0) { rs[wid] = s; rs2[wid] = s2; }
    __syncthreads();
    if (wid == 0) {
        s  = (lane < 8) ? rs[lane]  : 0.f;
        s2 = (lane < 8) ? rs2[lane] : 0.f;
        #pragma unroll
        for (int o = 4; o > 0; o >>= 1) {
            s  += __shfl_down_sync(0xFFFFFFFFu, s,  o);
            s2 += __shfl_down_sync(0xFFFFFFFFu, s2, o);
        }
        if (lane == 0) { rs[0] = s; rs2[0] = s2; }
    }
    __syncthreads();
    const float inv_n = 1.f / (float)(CPG * HW);
    const float mu   = rs[0] * inv_n;
    const float var  = rs2[0] * inv_n - mu * mu;
    const float rstd = rsqrtf(var + EPSV);

    __shared__ float ssc[CPG], ssh[CPG];
    if (tid < CPG) {
        int c = g * CPG + tid;
        float scv = rstd * gw[c];
        ssc[tid] = scv;
        ssh[tid] = gb[c] - mu * scv;
    }
    __syncthreads();

    __nv_bfloat16* xh = g_xh + base;
    __nv_bfloat16* xl = g_xl + base;
    #pragma unroll 8
    for (int it = 0; it < 32; it++) {
        int idx = it * 256 + tid;            // float4 index; 1024 per row
        int row = idx >> 10;
        float sc = ssc[row], sh = ssh[row];
        float4 v = *(const float4*)(xp + (size_t)idx * 4);
        v.x = fmaf(v.x, sc, sh); v.y = fmaf(v.y, sc, sh);
        v.z = fmaf(v.z, sc, sh); v.w = fmaf(v.w, sc, sh);
        __nv_bfloat16 h0 = __float2bfloat16(v.x), h1 = __float2bfloat16(v.y);
        __nv_bfloat16 h2 = __float2bfloat16(v.z), h3 = __float2bfloat16(v.w);
        __nv_bfloat16 l0 = __float2bfloat16(v.x - __bfloat162float(h0));
        __nv_bfloat16 l1 = __float2bfloat16(v.y - __bfloat162float(h1));
        __nv_bfloat16 l2 = __float2bfloat16(v.z - __bfloat162float(h2));
        __nv_bfloat16 l3 = __float2bfloat16(v.w - __bfloat162float(h3));
        *(uint2*)(xh + (size_t)idx * 4) = make_uint2(pk2(h0, h1), pk2(h2, h3));
        *(uint2*)(xl + (size_t)idx * 4) = make_uint2(pk2(l0, l1), pk2(l2, l3));
    }
}

// K1c: split + rearrange w_qkv K,V rows
__global__ __launch_bounds__(256) void prep_w_kernel(const float* __restrict__ w) {
    int idx = blockIdx.x * 256 + threadIdx.x;   // 0 .. 32767 float4s
    int r = idx >> 6, c4 = (idx & 63) * 4;
    int hh = r >> 8, rr = r & 255;
    int src = (rr < 128) ? (256 + hh * 128 + rr) : (512 + hh * 128 + rr - 128);
    float4 v = *(const float4*)(w + (size_t)src * CC + c4);
    __nv_bfloat16 h0 = __float2bfloat16(v.x), h1 = __float2bfloat16(v.y);
    __nv_bfloat16 h2 = __float2bfloat16(v.z), h3 = __float2bfloat16(v.w);
    __nv_bfloat16 l0 = __float2bfloat16(v.x - __bfloat162float(h0));
    __nv_bfloat16 l1 = __float2bfloat16(v.y - __bfloat162float(h1));
    __nv_bfloat16 l2 = __float2bfloat16(v.z - __bfloat162float(h2));
    __nv_bfloat16 l3 = __float2bfloat16(v.w - __bfloat162float(h3));
    size_t o = (size_t)r * CC + c4;
    *(uint2*)(g_wqh + o) = make_uint2(pk2(h0, h1), pk2(h2, h3));
    *(uint2*)(g_wql + o) = make_uint2(pk2(l0, l1), pk2(l2, l3));
}

// ---------------------------------------------------------------------------
// K2: fused KV GEMM + online attention partials (3-stage cp.async pipeline).
// ---------------------------------------------------------------------------
__global__ __launch_bounds__(512)
void gemm_kv_att() {
    extern __shared__ char smem[];
    const uint32_t sb = smem_u32(smem);

    const int tid = threadIdx.x;
    const int wid = tid >> 5, lane = tid & 31;
    const int wM = wid >> 1, wN = wid & 1;     // wM 0-3 = K rows, 4-7 = V rows
    const int s  = blockIdx.x;
    const int hh = blockIdx.y;
    const int b  = blockIdx.z;
    const int n0 = s * 128;

    const __nv_bfloat16* Ahb = g_wqh + (size_t)hh * 256 * CC;
    const __nv_bfloat16* Alb = g_wql + (size_t)hh * 256 * CC;
    const __nv_bfloat16* Bh  = g_xh + (size_t)b * CC * HW;
    const __nv_bfloat16* Bl  = g_xl + (size_t)b * CC * HW;

    const int bRowL0 = tid >> 4, bQ4 = (tid & 15) * 8;

    auto issue = [&](int kc, int stage) {
        const uint32_t st = sb + stage * F_STAGE;
        const int k0 = kc * 32;
        #pragma unroll
        for (int it = 0; it < 2; it++) {       // A: 1024 cp16 per plane
            int idx = it * 512 + tid;
            int row = idx >> 2, q4 = (idx & 3) * 8;
            uint32_t d = (uint32_t)(row * AST + q4) * 2;
            cp16(st + F_AH + d, Ahb + (size_t)row * CC + k0 + q4);
            cp16(st + F_AL + d, Alb + (size_t)row * CC + k0 + q4);
        }
        {                                      // B: 512 cp16 per plane
            size_t g = ((size_t)(k0 + bRowL0)) * HW + n0 + bQ4;
            uint32_t d = (uint32_t)(bRowL0 * BST + bQ4) * 2;
            cp16(st + F_BH + d, Bh + g);
            cp16(st + F_BL + d, Bl + g);
        }
        asm volatile("cp.async.commit_group;");
    };

    float acc[2][8][4];
    #pragma unroll
    for (int i = 0; i < 2; i++)
        #pragma unroll
        for (int j = 0; j < 8; j++)
            #pragma unroll
            for (int q = 0; q < 4; q++) acc[i][j][q] = 0.f;

    const int lt = lane >> 3, lr = lane & 7;
    const int aRow = lr + ((lt & 1) ? 8 : 0);
    const int aKof = (lt & 2) ? 8 : 0;
    const int bKof = lr + ((lt & 1) ? 8 : 0);
    const int bNof = (lt & 2) ? 8 : 0;

    issue(0, 0);
    issue(1, 1);

    for (int kc = 0; kc < 8; kc++) {
        const int stage = kc % 3;
        if (kc < 6) {
            issue(kc + 2, (kc + 2) % 3);
            asm volatile("cp.async.wait_group 2;");
        } else if (kc == 6) {
            asm volatile("cp.async.wait_group 1;");
        } else {
            asm volatile("cp.async.wait_group 0;");
        }
        __syncthreads();

        const uint32_t aHB = sb + stage * F_STAGE + F_AH;
        const uint32_t aLB = sb + stage * F_STAGE + F_AL;
        const uint32_t bHB = sb + stage * F_STAGE + F_BH;
        const uint32_t bLB = sb + stage * F_STAGE + F_BL;

        #pragma unroll
        for (int ks = 0; ks < 2; ks++) {
            const int kb = ks * 16;
            uint32_t ah[2][4], al[2][4], bh[8][2], bl[8][2];
            #pragma unroll
            for (int mt = 0; mt < 2; mt++) {
                uint32_t ad = ((wM * 32 + mt * 16 + aRow) * AST + kb + aKof) * 2;
                ldmx4(ah[mt], aHB + ad);
                ldmx4(al[mt], aLB + ad);
            }
            #pragma unroll
            for (int np = 0; np < 4; np++) {
                uint32_t bd = ((kb + bKof) * BST + wN * 64 + np * 16 + bNof) * 2;
                uint32_t r[4];
                ldmx4t(r, bHB + bd);
                bh[np * 2][0] = r[0]; bh[np * 2][1] = r[1];
                bh[np * 2 + 1][0] = r[2]; bh[np * 2 + 1][1] = r[3];
                ldmx4t(r, bLB + bd);
                bl[np * 2][0] = r[0]; bl[np * 2][1] = r[1];
                bl[np * 2 + 1][0] = r[2]; bl[np * 2 + 1][1] = r[3];
            }
            #pragma unroll
            for (int mt = 0; mt < 2; mt++)
                #pragma unroll
                for (int nt = 0; nt < 8; nt++) {
                    mma_bf16(acc[mt][nt], ah[mt], bh[nt]);
                    mma_bf16(acc[mt][nt], ah[mt], bl[nt]);
                    mma_bf16(acc[mt][nt], al[mt], bh[nt]);
                }
        }
        __syncthreads();
    }

    // ================= fused attention epilogue =================
    const int rq = lane >> 2, cq = lane & 3;
    const bool isK = (wM < 4);
    float* smMax = (float*)(smem + PMAX);  // [2][128]
    float* smSum = (float*)(smem + PSUM);  // [2][128]

    // 1. per-warp row max over this warp's 64 cols
    if (isK) {
        #pragma unroll
        for (int mt = 0; mt < 2; mt++)
            #pragma unroll
            for (int rh = 0; rh < 2; rh++) {
                float m = -3.4e38f;
                #pragma unroll
                for (int nt = 0; nt < 8; nt++) {
                    m = fmaxf(m, acc[mt][nt][rh * 2]);
                    m = fmaxf(m, acc[mt][nt][rh * 2 + 1]);
                }
                m = fmaxf(m, __shfl_xor_sync(0xFFFFFFFFu, m, 1));
                m = fmaxf(m, __shfl_xor_sync(0xFFFFFFFFu, m, 2));
                if (cq == 0)
                    smMax[wN * 128 + wM * 32 + mt * 16 + rh * 8 + rq] = m;
            }
    }
    __syncthreads();

    // 2. exp with combined max + row sums
    if (isK) {
        #pragma unroll
        for (int mt = 0; mt < 2; mt++)
            #pragma unroll
            for (int rh = 0; rh < 2; rh++) {
                int row = wM * 32 + mt * 16 + rh * 8 + rq;
                float km = fmaxf(smMax[row], smMax[128 + row]);
                float ss = 0.f;
                #pragma unroll
                for (int nt = 0; nt < 8; nt++) {
                    float e0 = __expf(acc[mt][nt][rh * 2]     - km);
                    float e1 = __expf(acc[mt][nt][rh * 2 + 1] - km);
                    acc[mt][nt][rh * 2]     = e0;
                    acc[mt][nt][rh * 2 + 1] = e1;
                    ss += e0 + e1;
                }
                ss += __shfl_xor_sync(0xFFFFFFFFu, ss, 1);
                ss += __shfl_xor_sync(0xFFFFFFFFu, ss, 2);
                if (cq == 0) smSum[wN * 128 + row] = ss;
            }
    }

    // 3. two n-passes: stage expK/V tiles (bf16 hi/lo) + P-MMA
    float pp[2][4];
    #pragma unroll
    for (int mt = 0; mt < 2; mt++)
        #pragma unroll
        for (int q = 0; q < 4; q++) pp[mt][q] = 0.f;

    const int head = wid >> 2, sub = wid & 3;
    const int l16 = lane & 15;
    const uint32_t baddrBase =
        ((head * 32 + sub * 8 + (l16 & 7)) * PST + (l16 >> 3) * 8) * 2;

    #pragma unroll
    for (int p = 0; p < 2; p++) {
        __syncthreads();
        if (wN == p) {
            const int rowb = (wM & 3) * 32;
            #pragma unroll
            for (int mt = 0; mt < 2; mt++)
                #pragma unroll
                for (int rh = 0; rh < 2; rh++) {
                    int row = rowb + mt * 16 + rh * 8 + rq;
                    #pragma unroll
                    for (int nt = 0; nt < 8; nt++) {
                        int c = nt * 8 + cq * 2;
                        float v0 = acc[mt][nt][rh * 2];
                        float v1 = acc[mt][nt][rh * 2 + 1];
                        __nv_bfloat16 h0 = __float2bfloat16(v0);
                        __nv_bfloat16 h1 = __float2bfloat16(v1);
                        __nv_bfloat16 q0 = __float2bfloat16(v0 - __bfloat162float(h0));
                        __nv_bfloat16 q1 = __float2bfloat16(v1 - __bfloat162float(h1));
                        uint32_t off = (uint32_t)(row * PST + c) * 2;
                        *(uint32_t*)(smem + (isK ? PKH : PVH) + off) = pk2(h0, h1);
                        *(uint32_t*)(smem + (isK ? PKL : PVL) + off) = pk2(q0, q1);
                    }
                }
        }
        __syncthreads();

        #pragma unroll
        for (int ks = 0; ks < 4; ks++) {
            const int kb = ks * 16;
            uint32_t b2h[2], b2l[2];
            ldmx2(b2h, sb + PVH + baddrBase + (uint32_t)kb * 2);
            ldmx2(b2l, sb + PVL + baddrBase + (uint32_t)kb * 2);
            #pragma unroll
            for (int mt = 0; mt < 2; mt++) {
                uint32_t a2h[4], a2l[4];
                uint32_t ad = ((head * 32 + mt * 16 + aRow) * PST + kb + aKof) * 2;
                ldmx4(a2h, sb + PKH + ad);
                ldmx4(a2l, sb + PKL + ad);
                mma_bf16(pp[mt], a2h, b2h);
                mma_bf16(pp[mt], a2h, b2l);
                mma_bf16(pp[mt], a2l, b2h);
            }
        }
    }

    // 4. write P partials ([bh][s][d*e]), lmax/lsum ([bh][s][d])
    const int bh = b * NH + hh * 4 + head;
    float* P = g_att_part + ((size_t)bh * SPLIT + s) * (HD * HD);
    #pragma unroll
    for (int mt = 0; mt < 2; mt++) {
        int d = mt * 16 + rq;
        int e = sub * 8 + cq * 2;
        *(float2*)&P[d * HD + e]       = make_float2(pp[mt][0], pp[mt][1]);
        *(float2*)&P[(d + 8) * HD + e] = make_float2(pp[mt][2], pp[mt][3]);
    }
    if (tid < 128) {
        int h = hh * 4 + (tid >> 5);
        int o = ((b * NH + h) * SPLIT + s) * HD + (tid & 31);
        g_lmax[o] = fmaxf(smMax[tid], smMax[128 + tid]);
        g_lsum[o] = smSum[tid] + smSum[128 + tid];
    }
}

// ---------------------------------------------------------------------------
// K3: fused split-combine + Weff slice.  One block per (b, h), 256 threads.
//   float4 reduce, unroll 16 for MLP; lmax/lsum now contiguous per bh.
// ---------------------------------------------------------------------------
__global__ __launch_bounds__(256) void att_weff_kernel(const float* __restrict__ wp) {
    const int bh = blockIdx.x;
    const int b = bh >> 3, h = bh & 7;
    const int t = threadIdx.x;

    __shared__ float satt[HD * HD];       // 4 KB
    __shared__ float sfac[SPLIT][HD];     // 4 KB
    __shared__ float sdinv[HD];

    if (t < HD) {
        const float* lm = g_lmax + (size_t)bh * SPLIT * HD + t;
        const float* ls = g_lsum + (size_t)bh * SPLIT * HD + t;
        float gm = -3.4e38f;
        #pragma unroll 8
        for (int s = 0; s < SPLIT; s++)
            gm = fmaxf(gm, lm[s * HD]);
        float den = 0.f;
        #pragma unroll 8
        for (int s = 0; s < SPLIT; s++) {
            float f = __expf(lm[s * HD] - gm);
            sfac[s][t] = f;
            den += ls[s * HD] * f;
        }
        sdinv[t] = 1.f / den;
    }
    __syncthreads();

    // float4 reduce: thread t covers floats [t*4, t*4+4), row d = t>>3
    const float4* P4 = (const float4*)(g_att_part + (size_t)bh * SPLIT * (HD * HD));
    const int d = t >> 3;
    float4 a4 = make_float4(0.f, 0.f, 0.f, 0.f);
    #pragma unroll 16
    for (int s = 0; s < SPLIT; s++) {
        float f = sfac[s][d];
        float4 p = P4[s * 256 + t];
        a4.x = fmaf(p.x, f, a4.x);
        a4.y = fmaf(p.y, f, a4.y);
        a4.z = fmaf(p.z, f, a4.z);
        a4.w = fmaf(p.w, f, a4.w);
    }
    {
        float di = sdinv[d];
        a4.x *= di; a4.y *= di; a4.z *= di; a4.w *= di;
        *(float4*)&satt[t * 4] = a4;
    }
    __syncthreads();

    // Weff slice: o = t, 32 outputs
    const float* wrow = wp + (size_t)t * CC + h * HD;
    float wreg[HD];
    #pragma unroll
    for (int e = 0; e < HD; e++) wreg[e] = wrow[e];
    float* wout = g_weff + ((size_t)b * CC + t) * CC + h * HD;
    #pragma unroll 2
    for (int d2 = 0; d2 < HD; d2++) {
        float sum = 0.f;
        #pragma unroll
        for (int e = 0; e < HD; e++)
            sum = fmaf(wreg[e], satt[d2 * HD + e], sum);
        wout[d2] = sum;
    }
}

// ---------------------------------------------------------------------------
// K4b: W2[b] = Weff[b] . Wq_q, split to bf16 hi/lo
// ---------------------------------------------------------------------------
__global__ __launch_bounds__(256) void w2_kernel(const float* __restrict__ wq) {
    __shared__ float sW[16 * 256];
    const int b = blockIdx.x, r0 = blockIdx.y * 16;
    const int t = threadIdx.x;

    const float4* src = (const float4*)(g_weff + ((size_t)b * CC + r0) * CC);
    #pragma unroll
    for (int i = 0; i < 4; i++)
        ((float4*)sW)[i * 256 + t] = src[i * 256 + t];
    __syncthreads();

    const int c = t;
    float acc[16];
    #pragma unroll
    for (int o = 0; o < 16; o++) acc[o] = 0.f;

    for (int d = 0; d < CC; d += 4) {
        float wv0 = wq[(size_t)(d + 0) * CC + c];
        float wv1 = wq[(size_t)(d + 1) * CC + c];
        float wv2 = wq[(size_t)(d + 2) * CC + c];
        float wv3 = wq[(size_t)(d + 3) * CC + c];
        #pragma unroll
        for (int o = 0; o < 16; o++) {
            float4 sw = *(const float4*)&sW[o * 256 + d];
            acc[o] = fmaf(sw.x, wv0, acc[o]);
            acc[o] = fmaf(sw.y, wv1, acc[o]);
            acc[o] = fmaf(sw.z, wv2, acc[o]);
            acc[o] = fmaf(sw.w, wv3, acc[o]);
        }
    }
    #pragma unroll
    for (int o = 0; o < 16; o++) {
        float v = acc[o];
        __nv_bfloat16 hh = __float2bfloat16(v);
        __nv_bfloat16 ll = __float2bfloat16(v - __bfloat162float(hh));
        size_t g = ((size_t)b * CC + r0 + o) * CC + c;
        g_w2h[g] = hh;
        g_w2l[g] = ll;
    }
}

// ---------------------------------------------------------------------------
// K5: final GEMM out = W2[b] @ xn + bias (256 threads, 3-stage cp.async)
// ---------------------------------------------------------------------------
__global__ __launch_bounds__(256)
void gemm_final(const float* __restrict__ bias, float* __restrict__ Cout) {
    extern __shared__ char smem[];
    const uint32_t sb = smem_u32(smem);

    const int tid = threadIdx.x;
    const int wid = tid >> 5, lane = tid & 31;
    const int wM = wid >> 1, wN = wid & 1;
    const int b  = blockIdx.z;
    const int m0 = blockIdx.y * 128;
    const int n0 = blockIdx.x * 128;

    const __nv_bfloat16* Ahb = g_w2h + (size_t)b * CC * CC;
    const __nv_bfloat16* Alb = g_w2l + (size_t)b * CC * CC;
    const __nv_bfloat16* Bh  = g_xh + (size_t)b * CC * HW;
    const __nv_bfloat16* Bl  = g_xl + (size_t)b * CC * HW;

    const int aRowL0 = tid >> 2, aQ4 = (tid & 3) * 8;
    const int bRowL0 = tid >> 4, bQ4 = (tid & 15) * 8;

    auto issue = [&](int kc, int stage) {
        const uint32_t st = sb + stage * ST_BYTES;
        const int k0 = kc * 32;
        #pragma unroll
        for (int it = 0; it < 2; it++) {
            int row = aRowL0 + it * 64;
            uint32_t d = (uint32_t)(row * AST + aQ4) * 2;
            cp16(st + ST_AH + d, Ahb + (size_t)(m0 + row) * CC + k0 + aQ4);
            cp16(st + ST_AL + d, Alb + (size_t)(m0 + row) * CC + k0 + aQ4);
        }
        #pragma unroll
        for (int it = 0; it < 2; it++) {
            int row = bRowL0 + it * 16;
            size_t g = ((size_t)(k0 + row)) * HW + n0 + bQ4;
            uint32_t d = (uint32_t)(row * BST + bQ4) * 2;
            cp16(st + ST_BH + d, Bh + g);
            cp16(st + ST_BL + d, Bl + g);
        }
        asm volatile("cp.async.commit_group;");
    };

    float acc[2][8][4];
    #pragma unroll
    for (int i = 0; i < 2; i++)
        #pragma unroll
        for (int j = 0; j < 8; j++)
            #pragma unroll
            for (int q = 0; q < 4; q++) acc[i][j][q] = 0.f;

    const int lt = lane >> 3, lr = lane & 7;
    const int aRow = lr + ((lt & 1) ? 8 : 0);
    const int aKof = (lt & 2) ? 8 : 0;
    const int bKof = lr + ((lt & 1) ? 8 : 0);
    const int bNof = (lt & 2) ? 8 : 0;

    issue(0, 0);
    issue(1, 1);

    for (int kc = 0; kc < 8; kc++) {
        const int stage = kc % 3;
        if (kc < 6) {
            issue(kc + 2, (kc + 2) % 3);
            asm volatile("cp.async.wait_group 2;");
        } else if (kc == 6) {
            asm volatile("cp.async.wait_group 1;");
        } else {
            asm volatile("cp.async.wait_group 0;");
        }
        __syncthreads();

        const uint32_t aHB = sb + stage * ST_BYTES + ST_AH;
        const uint32_t aLB = sb + stage * ST_BYTES + ST_AL;
        const uint32_t bHB = sb + stage * ST_BYTES + ST_BH;
        const uint32_t bLB = sb + stage * ST_BYTES + ST_BL;

        #pragma unroll
        for (int ks = 0; ks < 2; ks++) {
            const int kb = ks * 16;
            uint32_t ah[2][4], al[2][4], bh[8][2], bl[8][2];
            #pragma unroll
            for (int mt = 0; mt < 2; mt++) {
                uint32_t ad = ((wM * 32 + mt * 16 + aRow) * AST + kb + aKof) * 2;
                ldmx4(ah[mt], aHB + ad);
                ldmx4(al[mt], aLB + ad);
            }
            #pragma unroll
            for (int np = 0; np < 4; np++) {
                uint32_t bd = ((kb + bKof) * BST + wN * 64 + np * 16 + bNof) * 2;
                uint32_t r[4];
                ldmx4t(r, bHB + bd);
                bh[np * 2][0] = r[0]; bh[np * 2][1] = r[1];
                bh[np * 2 + 1][0] = r[2]; bh[np * 2 + 1][1] = r[3];
                ldmx4t(r, bLB + bd);
                bl[np * 2][0] = r[0]; bl[np * 2][1] = r[1];
                bl[np * 2 + 1][0] = r[2]; bl[np * 2 + 1][1] = r[3];
            }
            #pragma unroll
            for (int mt = 0; mt < 2; mt++)
                #pragma unroll
                for (int nt = 0; nt < 8; nt++) {
                    mma_bf16(acc[mt][nt], ah[mt], bh[nt]);
                    mma_bf16(acc[mt][nt], ah[mt], bl[nt]);
                    mma_bf16(acc[mt][nt], al[mt], bh[nt]);
                }
        }
        __syncthreads();
    }

    const int rbase = m0 + wM * 32 + (lane >> 2);
    const int cbase = n0 + wN * 64 + (lane & 3) * 2;
    #pragma unroll
    for (int mt = 0; mt < 2; mt++) {
        int r0 = rbase + mt * 16;
        float bi0 = bias[r0];
        float bi1 = bias[r0 + 8];
        #pragma unroll
        for (int nt = 0; nt < 8; nt++) {
            int cc = cbase + nt * 8;
            *(float2*)(Cout + ((size_t)b * CC + r0) * HW + cc) =
                make_float2(acc[mt][nt][0] + bi0, acc[mt][nt][1] + bi0);
            *(float2*)(Cout + ((size_t)b * CC + r0 + 8) * HW + cc) =
                make_float2(acc[mt][nt][2] + bi1, acc[mt][nt][3] + bi1);
        }
    }
}

// ---------------------------------------------------------------------------
extern "C" void kernel_launch(void* const* d_in, const int* in_sizes, int n_in,
                              void* d_out, int out_size) {
    const float* x      = (const float*)d_in[0];
    const float* gn_w   = (const float*)d_in[1];
    const float* gn_b   = (const float*)d_in[2];
    const float* w_qkv  = (const float*)d_in[3];
    const float* w_proj = (const float*)d_in[4];
    const float* b_proj = (const float*)d_in[5];
    float* out = (float*)d_out;

    cudaFuncSetAttribute(gemm_kv_att, cudaFuncAttributeMaxDynamicSharedMemorySize,
                         F_SMEM);
    cudaFuncSetAttribute(gemm_final, cudaFuncAttributeMaxDynamicSharedMemorySize,
                         SMEM_GEMM);

    // K1: fused groupnorm + split x; split+rearrange K/V weights
    prep_w_kernel<<<128, 256>>>(w_qkv);
    gn_prep_kernel<<<BB * NG, 256>>>(x, gn_w, gn_b);

    // K2: fused KV projection + attention partials
    {
        dim3 grid(SPLIT, 2, BB);
        gemm_kv_att<<<grid, 512, F_SMEM>>>();
    }

    // K3: combine splits + fold into Wp (per (b,h))
    att_weff_kernel<<<BB * NH, 256>>>(w_proj);

    // K4: W2 = Weff . Wq_q
    {
        dim3 grid(BB, CC / 16);
        w2_kernel<<<grid, 256>>>(w_qkv);
    }

    // K5: out = W2[b] @ xn + bias
    {
        dim3 grid(HW / 128, CC / 128, BB);
        gemm_final<<<grid, 256, SMEM_GEMM>>>(b_proj, out);
    }
}